// round 1
// baseline (speedup 1.0000x reference)
#include <cuda_runtime.h>
#include <math.h>

#define FDIM 128
#define SSCALE 1.6666666666666667f   // 1/0.6
#define INV3 0.5773502691896258f     // 1/sqrt(3)
#define INVH 0.08838834764831845f    // 1/sqrt(128)

// Scratch: 8*N*F node buffers + ~2.1M floats for global phase (N<=120000)
static __device__ float g_buf[125000000];

__device__ __forceinline__ float ssilu_f(float v) {
    return v * SSCALE / (1.0f + __expf(-v));
}

// ---------------------------------------------------------------------------
// Tiled SGEMM: C[M,Cc] = A[M,K] @ W[K,Cc]  (+ fused epilogues)
// BM=128, BN=128, BK=8, 256 threads, 8x8 per thread.
// EPI: 0=plain 1=+bias 2=ssilu(+bias) 3=ssilu(+extra[batch[r]*128+c])
//      4=ssilu(+bias)+extra[r*128+c]  5=+extra[r*128+c]
// ---------------------------------------------------------------------------
template <int EPI>
__global__ void __launch_bounds__(256) sgemm_k(
    const float* __restrict__ A, const float* __restrict__ W,
    const float* __restrict__ bias, float* __restrict__ C,
    int M, int K, int Cc,
    const float* __restrict__ extra, const int* __restrict__ bidx)
{
    __shared__ float As[8][128];
    __shared__ float Ws[8][128];
    const int tid = threadIdx.x;
    const int row0 = blockIdx.x * 128;
    const int col0 = blockIdx.y * 128;
    const int tx = tid & 15;       // 16 col groups
    const int ty = tid >> 4;       // 16 row groups
    const int arow = tid >> 1;
    const int ak = (tid & 1) * 4;
    const int wk = tid >> 5;
    const int wc = (tid & 31) * 4;

    float acc[8][8];
    #pragma unroll
    for (int i = 0; i < 8; i++)
        #pragma unroll
        for (int j = 0; j < 8; j++) acc[i][j] = 0.0f;

    for (int k0 = 0; k0 < K; k0 += 8) {
        float4 av;
        int grow = row0 + arow;
        if (grow < M)
            av = *reinterpret_cast<const float4*>(A + (size_t)grow * K + k0 + ak);
        else
            av = make_float4(0.f, 0.f, 0.f, 0.f);
        As[ak + 0][arow] = av.x;
        As[ak + 1][arow] = av.y;
        As[ak + 2][arow] = av.z;
        As[ak + 3][arow] = av.w;

        float4 wv = *reinterpret_cast<const float4*>(
            W + (size_t)(k0 + wk) * Cc + col0 + wc);
        *reinterpret_cast<float4*>(&Ws[wk][wc]) = wv;
        __syncthreads();

        #pragma unroll
        for (int k = 0; k < 8; k++) {
            float ra[8], rb[8];
            #pragma unroll
            for (int i = 0; i < 4; i++) {
                float4 t4 = *reinterpret_cast<const float4*>(&As[k][ty * 8 + i * 4]);
                ra[i * 4 + 0] = t4.x; ra[i * 4 + 1] = t4.y;
                ra[i * 4 + 2] = t4.z; ra[i * 4 + 3] = t4.w;
            }
            #pragma unroll
            for (int j = 0; j < 4; j++) {
                float4 t4 = *reinterpret_cast<const float4*>(&Ws[k][tx * 8 + j * 4]);
                rb[j * 4 + 0] = t4.x; rb[j * 4 + 1] = t4.y;
                rb[j * 4 + 2] = t4.z; rb[j * 4 + 3] = t4.w;
            }
            #pragma unroll
            for (int i = 0; i < 8; i++)
                #pragma unroll
                for (int j = 0; j < 8; j++)
                    acc[i][j] += ra[i] * rb[j];
        }
        __syncthreads();
    }

    #pragma unroll
    for (int i = 0; i < 8; i++) {
        int r = row0 + ty * 8 + i;
        if (r >= M) continue;
        int rb = 0;
        if (EPI == 3) rb = bidx[r];
        #pragma unroll
        for (int j = 0; j < 8; j++) {
            int c = col0 + tx * 8 + j;
            float v = acc[i][j];
            if (EPI == 1) v += bias[c];
            else if (EPI == 2) v = ssilu_f(v + bias[c]);
            else if (EPI == 3) v = ssilu_f(v + extra[(size_t)rb * 128 + c]);
            else if (EPI == 4) v = ssilu_f(v + bias[c]) + extra[(size_t)r * 128 + c];
            else if (EPI == 5) v = v + extra[(size_t)r * 128 + c];
            C[(size_t)r * Cc + c] = v;
        }
    }
}

// ---------------------------------------------------------------------------
// Node-level elementwise fusion.
// vecn may alias ep, vtmp may alias xp (each thread reads its 3 addrs first).
// ---------------------------------------------------------------------------
__global__ void node_elem_k(
    const float* xp, const float* ep, const float* x,
    const float* vec, const float* ud, const float* vl_g,
    const int* batch, float* xn, float* vecn, float* vtmp, int N)
{
    int idx = blockIdx.x * blockDim.x + threadIdx.x;
    if (idx >= N * FDIM) return;
    int n = idx >> 7;
    int f = idx & 127;
    size_t b3 = (size_t)n * 384;

    float e1 = ep[b3 + f], e2 = ep[b3 + 128 + f], e3 = ep[b3 + 256 + f];
    float a1 = xp[b3 + f], a2 = xp[b3 + 128 + f], a3 = xp[b3 + 256 + f];
    float p1 = a1 * e1 * INV3;
    float p2 = a2 * e2 * INV3;
    float p3 = a3 * e3 * INV3;

    xn[(size_t)n * 128 + f] = p3 + x[(size_t)n * 128 + f];

    int b = batch[n];
    float u0 = ud[n * 3 + 0], u1 = ud[n * 3 + 1], u2 = ud[n * 3 + 2];
    float v0 = vec[b3 + 0 * 128 + f];
    float v1 = vec[b3 + 1 * 128 + f];
    float v2 = vec[b3 + 2 * 128 + f];
    float g0 = vl_g[(size_t)b * 384 + 0 * 128 + f];
    float g1 = vl_g[(size_t)b * 384 + 1 * 128 + f];
    float g2 = vl_g[(size_t)b * 384 + 2 * 128 + f];

    float n0 = (p1 * v0 + p2 * u0) * INVH;
    float n1 = (p1 * v1 + p2 * u1) * INVH;
    float n2 = (p1 * v2 + p2 * u2) * INVH;
    vecn[b3 + 0 * 128 + f] = n0;
    vecn[b3 + 1 * 128 + f] = n1;
    vecn[b3 + 2 * 128 + f] = n2;
    vtmp[b3 + 0 * 128 + f] = n0 + g0;
    vtmp[b3 + 1 * 128 + f] = n1 + g1;
    vtmp[b3 + 2 * 128 + f] = n2 + g2;
}

// Zero the accumulators
__global__ void zero_k(float* p, int n) {
    int i = blockIdx.x * blockDim.x + threadIdx.x;
    if (i < n) p[i] = 0.0f;
}

__global__ void counts_k(const int* batch, float* cnt, int N) {
    int i = blockIdx.x * blockDim.x + threadIdx.x;
    if (i < N) atomicAdd(&cnt[batch[i]], 1.0f);
}

// Sorted-segment sum: block handles [r0,r1) rows, thread = one column.
__global__ void seg_reduce_k(const float* src, const int* batch, float* dst,
                             int N, int Cc, int rows_per_blk)
{
    int c = threadIdx.x;
    int r0 = blockIdx.x * rows_per_blk;
    if (r0 >= N) return;
    int r1 = min(r0 + rows_per_blk, N);
    int cur = batch[r0];
    float s = 0.0f;
    for (int r = r0; r < r1; r++) {
        int b = batch[r];
        if (b != cur) {
            atomicAdd(&dst[(size_t)cur * Cc + c], s);
            s = 0.0f;
            cur = b;
        }
        s += src[(size_t)r * Cc + c];
    }
    atomicAdd(&dst[(size_t)cur * Cc + c], s);
}

// Global phase elementwise kernels (B*128 threads each)
__global__ void g1_k(const float* sum_x, const float* sum_vec, const float* cnt,
                     const float* scalar_l, const float* vector_l,
                     float* gcat, float* Av, int B)
{
    int idx = blockIdx.x * blockDim.x + threadIdx.x;
    if (idx >= B * 128) return;
    int b = idx >> 7, f = idx & 127;
    float invc = 1.0f / fmaxf(cnt[b], 1.0f);
    gcat[(size_t)b * 256 + f] = sum_x[(size_t)b * 128 + f] * invc;
    gcat[(size_t)b * 256 + 128 + f] = scalar_l[(size_t)b * 128 + f];
    #pragma unroll
    for (int d = 0; d < 3; d++) {
        size_t o = (size_t)b * 384 + d * 128 + f;
        Av[o] = sum_vec[o] * invc + vector_l[o];
    }
}

__global__ void g2_k(const float* scalar_l, const float* stmp,
                     const float* vector_l, const float* vtmpB,
                     float* sl, float* vl, int B)
{
    int idx = blockIdx.x * blockDim.x + threadIdx.x;
    if (idx >= B * 128) return;
    int b = idx >> 7, f = idx & 127;
    sl[(size_t)b * 128 + f] = scalar_l[(size_t)b * 128 + f] + stmp[(size_t)b * 128 + f];
    #pragma unroll
    for (int d = 0; d < 3; d++) {
        size_t o = (size_t)b * 384 + d * 128 + f;
        vl[o] = vector_l[o] + vtmpB[o];
    }
}

__global__ void g3_k(const float* hh, const float* sl, float* cat2, int B)
{
    int idx = blockIdx.x * blockDim.x + threadIdx.x;
    if (idx >= B * 128) return;
    int b = idx >> 7, f = idx & 127;
    float s = 1e-8f;
    #pragma unroll
    for (int d = 0; d < 3; d++) {
        float h2 = hh[((size_t)b * 3 + d) * 256 + 128 + f];
        s += h2 * h2;
    }
    cat2[(size_t)b * 256 + f] = sl[(size_t)b * 128 + f];
    cat2[(size_t)b * 256 + 128 + f] = sqrtf(s);
}

__global__ void g4_k(const float* sh, const float* sl, const float* hh,
                     const float* vl, float* out_sl, float* out_vl, int B)
{
    int idx = blockIdx.x * blockDim.x + threadIdx.x;
    if (idx >= B * 128) return;
    int b = idx >> 7, f = idx & 127;
    float s1 = sh[(size_t)b * 384 + f];
    float s2 = sh[(size_t)b * 384 + 128 + f];
    float s3 = sh[(size_t)b * 384 + 256 + f];
    out_sl[(size_t)b * 128 + f] = s2 + sl[(size_t)b * 128 + f] * tanhf(s3);
    #pragma unroll
    for (int d = 0; d < 3; d++) {
        float h1 = hh[((size_t)b * 3 + d) * 256 + f];
        size_t o = (size_t)b * 384 + d * 128 + f;
        out_vl[o] = s1 * h1 + vl[o];
    }
}

__global__ void ldelta_k(const float* vl_out, const float* W_ml, float* out, int rows)
{
    int warp = (blockIdx.x * blockDim.x + threadIdx.x) >> 5;
    int lane = threadIdx.x & 31;
    if (warp >= rows) return;
    const float* r = vl_out + (size_t)warp * 128;
    float s = 0.0f;
    #pragma unroll
    for (int i = 0; i < 4; i++) s += r[lane + i * 32] * W_ml[lane + i * 32];
    #pragma unroll
    for (int o = 16; o; o >>= 1) s += __shfl_down_sync(0xffffffff, s, o);
    if (lane == 0) out[warp] = s;
}

// ---------------------------------------------------------------------------
extern "C" void kernel_launch(void* const* d_in, const int* in_sizes, int n_in,
                              void* d_out, int out_size)
{
    const float* x        = (const float*)d_in[0];
    const float* scalar_l = (const float*)d_in[1];
    const float* vec      = (const float*)d_in[2];
    const float* vector_l = (const float*)d_in[3];
    const float* edge_f   = (const float*)d_in[4];
    const float* edge_ud  = (const float*)d_in[5];
    const int*   batch    = (const int*)d_in[6];
    const float* W_sg1 = (const float*)d_in[7];  const float* b_sg1 = (const float*)d_in[8];
    const float* W_sg2 = (const float*)d_in[9];  const float* b_sg2 = (const float*)d_in[10];
    const float* W_sl1 = (const float*)d_in[11]; const float* b_sl1 = (const float*)d_in[12];
    const float* W_sl2 = (const float*)d_in[13]; const float* b_sl2 = (const float*)d_in[14];
    const float* W_vg  = (const float*)d_in[15];
    const float* W_vl  = (const float*)d_in[16];
    const float* W_xp1 = (const float*)d_in[17]; const float* b_xp1 = (const float*)d_in[18];
    const float* W_xp2 = (const float*)d_in[19]; const float* b_xp2 = (const float*)d_in[20];
    const float* W_ep  = (const float*)d_in[21]; const float* b_ep  = (const float*)d_in[22];
    const float* W_vp  = (const float*)d_in[23];
    const float* W_lp1 = (const float*)d_in[24]; const float* b_lp1 = (const float*)d_in[25];
    const float* W_lp2 = (const float*)d_in[26]; const float* b_lp2 = (const float*)d_in[27];
    const float* W_ml  = (const float*)d_in[28];

    const int N = in_sizes[0] / FDIM;
    const int B = in_sizes[1] / FDIM;
    const int K_edge = in_sizes[4] / N;   // R = 64

    float* base = nullptr;
    cudaGetSymbolAddress((void**)&base, g_buf);

    const size_t NF = (size_t)N * FDIM;
    // Scratch layout (with in-kernel-safe aliasing)
    float* t_buf  = base;                 // [N,F]   t, later u
    float* xp_buf = base + NF;            // [N,3F]  xp, later vtmp
    float* ep_buf = base + 4 * NF;        // [N,3F]  ep, later vecn
    float* xn_buf = base + 7 * NF;        // [N,F]
    float* sm     = base + 8 * NF;        // small buffers
    float* sB      = sm;                       // B*128
    float* sum_x   = sm + 65536;               // B*128
    float* sum_vec = sm + 131072;              // B*384
    float* cnt     = sm + 327680;              // B
    float* gcat    = sm + 328192;              // B*256
    float* Av      = sm + 459264;              // B*384
    float* tmp1    = sm + 655872;              // B*128
    float* stmp    = sm + 721408;              // B*128
    float* vtmpB   = sm + 786944;              // B*384
    float* sl      = sm + 983552;              // B*128
    float* vl      = sm + 1049088;             // B*384
    float* hh      = sm + 1245696;             // B*3*256
    float* cat2    = sm + 1638912;             // B*256
    float* t2      = sm + 1769984;             // B*128
    float* sh      = sm + 1835520;             // B*384

    float* out = (float*)d_out;
    const size_t o0 = 0;
    const size_t o1 = NF;                          // hvec
    const size_t o2 = o1 + 3 * NF;                 // sl_out
    const size_t o3 = o2 + (size_t)B * 128;        // vl_out
    const size_t o4 = o3 + (size_t)B * 384;        // l_delta

    const int gM_N   = (N + 127) / 128;
    const int gM_3N  = (3 * N + 127) / 128;
    const int gM_B   = (B + 127) / 128;
    const int gM_3B  = (3 * B + 127) / 128;

    // ---- node phase ----
    // t = ssilu(x @ W_xp1 + b_xp1)
    sgemm_k<2><<<dim3(gM_N, 1), 256>>>(x, W_xp1, b_xp1, t_buf, N, 128, 128, nullptr, nullptr);
    // xp = t @ W_xp2 + b_xp2
    sgemm_k<1><<<dim3(gM_N, 3), 256>>>(t_buf, W_xp2, b_xp2, xp_buf, N, 128, 384, nullptr, nullptr);
    // ep = edge_feat @ W_ep + b_ep
    sgemm_k<1><<<dim3(gM_N, 3), 256>>>(edge_f, W_ep, b_ep, ep_buf, N, K_edge, 384, nullptr, nullptr);
    // elementwise: xn, vecn(->ep_buf), vtmp(->xp_buf)
    {
        int tot = N * FDIM;
        node_elem_k<<<(tot + 255) / 256, 256>>>(xp_buf, ep_buf, x, vec, edge_ud,
                                                vector_l, batch, xn_buf, ep_buf, xp_buf, N);
    }
    // sB = scalar_l @ W_sl1[F:] + b_sl1
    sgemm_k<1><<<dim3(gM_B, 1), 256>>>(scalar_l, W_sl1 + 128 * 128, b_sl1, sB, B, 128, 128, nullptr, nullptr);
    // u = ssilu(xn @ W_sl1[:F] + sB[batch])   (into t_buf)
    sgemm_k<3><<<dim3(gM_N, 1), 256>>>(xn_buf, W_sl1, nullptr, t_buf, N, 128, 128, sB, batch);
    // hx = ssilu(u @ W_sl2 + b_sl2) + xn   -> d_out[o0]
    sgemm_k<4><<<dim3(gM_N, 1), 256>>>(t_buf, W_sl2, b_sl2, out + o0, N, 128, 128, xn_buf, nullptr);
    // hvec = vtmp @ W_vl + vecn            -> d_out[o1]
    sgemm_k<5><<<dim3(gM_3N, 1), 256>>>(xp_buf, W_vl, nullptr, out + o1, 3 * N, 128, 128, ep_buf, nullptr);

    // ---- segment reduction ----
    {
        int nz = B * 128 + B * 384 + B;
        zero_k<<<(nz + 255) / 256, 256>>>(sum_x, nz);  // sum_x, sum_vec, cnt are contiguous
        counts_k<<<(N + 255) / 256, 256>>>(batch, cnt, N);
        int rpb1 = 256;
        seg_reduce_k<<<(N + rpb1 - 1) / rpb1, 128>>>(out + o0, batch, sum_x, N, 128, rpb1);
        int rpb2 = 128;
        seg_reduce_k<<<(N + rpb2 - 1) / rpb2, 384>>>(out + o1, batch, sum_vec, N, 384, rpb2);
    }

    // ---- global phase ----
    int tB = B * 128;
    g1_k<<<(tB + 255) / 256, 256>>>(sum_x, sum_vec, cnt, scalar_l, vector_l, gcat, Av, B);
    sgemm_k<2><<<dim3(gM_B, 1), 256>>>(gcat, W_sg1, b_sg1, tmp1, B, 256, 128, nullptr, nullptr);
    sgemm_k<2><<<dim3(gM_B, 1), 256>>>(tmp1, W_sg2, b_sg2, stmp, B, 128, 128, nullptr, nullptr);
    sgemm_k<0><<<dim3(gM_3B, 1), 256>>>(Av, W_vg, nullptr, vtmpB, 3 * B, 128, 128, nullptr, nullptr);
    g2_k<<<(tB + 255) / 256, 256>>>(scalar_l, stmp, vector_l, vtmpB, sl, vl, B);
    sgemm_k<0><<<dim3(gM_3B, 2), 256>>>(vl, W_vp, nullptr, hh, 3 * B, 128, 256, nullptr, nullptr);
    g3_k<<<(tB + 255) / 256, 256>>>(hh, sl, cat2, B);
    sgemm_k<2><<<dim3(gM_B, 1), 256>>>(cat2, W_lp1, b_lp1, t2, B, 256, 128, nullptr, nullptr);
    sgemm_k<1><<<dim3(gM_B, 3), 256>>>(t2, W_lp2, b_lp2, sh, B, 128, 384, nullptr, nullptr);
    g4_k<<<(tB + 255) / 256, 256>>>(sh, sl, hh, vl, out + o2, out + o3, B);
    {
        int rows = 3 * B;
        int thr = 256;
        int blks = (rows * 32 + thr - 1) / thr;
        ldelta_k<<<blks, thr>>>(out + o3, W_ml, out + o4, rows);
    }
}

// round 2
// speedup vs baseline: 1.7239x; 1.7239x over previous
#include <cuda_runtime.h>
#include <math.h>
#include <stdint.h>

#define FDIM 128
#define SSCALE 1.6666666666666667f   // 1/0.6
#define INV3 0.5773502691896258f     // 1/sqrt(3)
#define INVH 0.08838834764831845f    // 1/sqrt(128)

// Scratch: 8*N*F node buffers + ~2.1M floats for global phase (N<=120000)
static __device__ float g_buf[125000000];

__device__ __forceinline__ float ssilu_f(float v) {
    return v * SSCALE / (1.0f + __expf(-v));
}

__device__ __forceinline__ uint32_t to_tf32_bits(float x) {
    uint32_t r;
    asm("cvt.rna.tf32.f32 %0, %1;" : "=r"(r) : "f"(x));
    return r;
}

__device__ __forceinline__ void mma_tf32(float* d,
                                         const uint32_t* a,
                                         const uint32_t* b,
                                         const float* c) {
    asm volatile(
        "mma.sync.aligned.m16n8k8.row.col.f32.tf32.tf32.f32 "
        "{%0,%1,%2,%3},{%4,%5,%6,%7},{%8,%9},{%10,%11,%12,%13};"
        : "=f"(d[0]), "=f"(d[1]), "=f"(d[2]), "=f"(d[3])
        : "r"(a[0]), "r"(a[1]), "r"(a[2]), "r"(a[3]),
          "r"(b[0]), "r"(b[1]),
          "f"(c[0]), "f"(c[1]), "f"(c[2]), "f"(c[3]));
}

// ---------------------------------------------------------------------------
// Tensor-core tf32 GEMM: C[M,Cc] = A[M,K] @ W[K,Cc]  (+ fused epilogues)
// BM=128, BN=128, BK=16, 256 threads (8 warps, 2M x 4N), warp tile 64x32.
// EPI: 0=plain 1=+bias 2=ssilu(+bias) 3=ssilu(+extra[bidx[r]*128+c])
//      4=ssilu(+bias)+extra[r*128+c]  5=+extra[r*128+c]
// Requires K % 16 == 0, Cc % 128 == 0.
// ---------------------------------------------------------------------------
template <int EPI>
__global__ void __launch_bounds__(256) tgemm_k(
    const float* __restrict__ A, const float* __restrict__ W,
    const float* __restrict__ bias, float* __restrict__ C,
    int M, int K, int Cc,
    const float* __restrict__ extra, const int* __restrict__ bidx)
{
    __shared__ float As[16][136];   // [k][m], pad 8 -> frag reads conflict-free
    __shared__ float Ws[16][136];   // [k][n]

    const int tid = threadIdx.x;
    const int row0 = blockIdx.x * 128;
    const int col0 = blockIdx.y * 128;
    const int warp = tid >> 5;
    const int lane = tid & 31;
    const int wm = warp & 1;        // 0..1  -> 64-row slab
    const int wn = warp >> 1;       // 0..3  -> 32-col slab
    const int g = lane >> 2;        // groupID 0..7
    const int tig = lane & 3;       // thread-in-group 0..3

    float acc[4][4][4];
    #pragma unroll
    for (int i = 0; i < 4; i++)
        #pragma unroll
        for (int j = 0; j < 4; j++)
            #pragma unroll
            for (int q = 0; q < 4; q++) acc[i][j][q] = 0.0f;

    for (int k0 = 0; k0 < K; k0 += 16) {
        // Load A tile: 128 rows x 16 k, float4 along K. 512 tasks, 2/thread.
        #pragma unroll
        for (int t = 0; t < 2; t++) {
            int id = tid + t * 256;
            int row = id >> 2;
            int kc = (id & 3) * 4;
            float4 av;
            int grow = row0 + row;
            if (grow < M)
                av = *reinterpret_cast<const float4*>(A + (size_t)grow * K + k0 + kc);
            else
                av = make_float4(0.f, 0.f, 0.f, 0.f);
            As[kc + 0][row] = __uint_as_float(to_tf32_bits(av.x));
            As[kc + 1][row] = __uint_as_float(to_tf32_bits(av.y));
            As[kc + 2][row] = __uint_as_float(to_tf32_bits(av.z));
            As[kc + 3][row] = __uint_as_float(to_tf32_bits(av.w));
        }
        // Load W tile: 16 k x 128 cols, float4 along cols. 512 tasks, 2/thread.
        #pragma unroll
        for (int t = 0; t < 2; t++) {
            int id = tid + t * 256;
            int kr = id >> 5;
            int c4 = (id & 31) * 4;
            float4 wv = *reinterpret_cast<const float4*>(
                W + (size_t)(k0 + kr) * Cc + col0 + c4);
            Ws[kr][c4 + 0] = __uint_as_float(to_tf32_bits(wv.x));
            Ws[kr][c4 + 1] = __uint_as_float(to_tf32_bits(wv.y));
            Ws[kr][c4 + 2] = __uint_as_float(to_tf32_bits(wv.z));
            Ws[kr][c4 + 3] = __uint_as_float(to_tf32_bits(wv.w));
        }
        __syncthreads();

        #pragma unroll
        for (int s = 0; s < 2; s++) {
            const int kb = s * 8;
            uint32_t afr[4][4];
            uint32_t bfr[4][2];
            #pragma unroll
            for (int mi = 0; mi < 4; mi++) {
                int mr = wm * 64 + mi * 16 + g;
                afr[mi][0] = __float_as_uint(As[kb + tig][mr]);
                afr[mi][1] = __float_as_uint(As[kb + tig][mr + 8]);
                afr[mi][2] = __float_as_uint(As[kb + tig + 4][mr]);
                afr[mi][3] = __float_as_uint(As[kb + tig + 4][mr + 8]);
            }
            #pragma unroll
            for (int nj = 0; nj < 4; nj++) {
                int nc = wn * 32 + nj * 8 + g;
                bfr[nj][0] = __float_as_uint(Ws[kb + tig][nc]);
                bfr[nj][1] = __float_as_uint(Ws[kb + tig + 4][nc]);
            }
            #pragma unroll
            for (int mi = 0; mi < 4; mi++)
                #pragma unroll
                for (int nj = 0; nj < 4; nj++)
                    mma_tf32(acc[mi][nj], afr[mi], bfr[nj], acc[mi][nj]);
        }
        __syncthreads();
    }

    // Epilogue
    #pragma unroll
    for (int mi = 0; mi < 4; mi++) {
        int rbase = row0 + wm * 64 + mi * 16 + g;
        #pragma unroll
        for (int half = 0; half < 2; half++) {
            int r = rbase + half * 8;
            if (r >= M) continue;
            int rb = 0;
            if (EPI == 3) rb = bidx[r];
            #pragma unroll
            for (int nj = 0; nj < 4; nj++) {
                int c = col0 + wn * 32 + nj * 8 + tig * 2;
                #pragma unroll
                for (int e = 0; e < 2; e++) {
                    float v = acc[mi][nj][half * 2 + e];
                    int cc = c + e;
                    if (EPI == 1) v += bias[cc];
                    else if (EPI == 2) v = ssilu_f(v + bias[cc]);
                    else if (EPI == 3) v = ssilu_f(v + extra[(size_t)rb * 128 + cc]);
                    else if (EPI == 4) v = ssilu_f(v + bias[cc]) + extra[(size_t)r * 128 + cc];
                    else if (EPI == 5) v = v + extra[(size_t)r * 128 + cc];
                    C[(size_t)r * Cc + cc] = v;
                }
            }
        }
    }
}

// ---------------------------------------------------------------------------
// Node-level elementwise fusion.
// vecn may alias ep, vtmp may alias xp (each thread reads its 3 addrs first).
// ---------------------------------------------------------------------------
__global__ void node_elem_k(
    const float* xp, const float* ep, const float* x,
    const float* vec, const float* ud, const float* vl_g,
    const int* batch, float* xn, float* vecn, float* vtmp, int N)
{
    int idx = blockIdx.x * blockDim.x + threadIdx.x;
    if (idx >= N * FDIM) return;
    int n = idx >> 7;
    int f = idx & 127;
    size_t b3 = (size_t)n * 384;

    float e1 = ep[b3 + f], e2 = ep[b3 + 128 + f], e3 = ep[b3 + 256 + f];
    float a1 = xp[b3 + f], a2 = xp[b3 + 128 + f], a3 = xp[b3 + 256 + f];
    float p1 = a1 * e1 * INV3;
    float p2 = a2 * e2 * INV3;
    float p3 = a3 * e3 * INV3;

    xn[(size_t)n * 128 + f] = p3 + x[(size_t)n * 128 + f];

    int b = batch[n];
    float u0 = ud[n * 3 + 0], u1 = ud[n * 3 + 1], u2 = ud[n * 3 + 2];
    float v0 = vec[b3 + 0 * 128 + f];
    float v1 = vec[b3 + 1 * 128 + f];
    float v2 = vec[b3 + 2 * 128 + f];
    float g0 = vl_g[(size_t)b * 384 + 0 * 128 + f];
    float g1 = vl_g[(size_t)b * 384 + 1 * 128 + f];
    float g2 = vl_g[(size_t)b * 384 + 2 * 128 + f];

    float n0 = (p1 * v0 + p2 * u0) * INVH;
    float n1 = (p1 * v1 + p2 * u1) * INVH;
    float n2 = (p1 * v2 + p2 * u2) * INVH;
    vecn[b3 + 0 * 128 + f] = n0;
    vecn[b3 + 1 * 128 + f] = n1;
    vecn[b3 + 2 * 128 + f] = n2;
    vtmp[b3 + 0 * 128 + f] = n0 + g0;
    vtmp[b3 + 1 * 128 + f] = n1 + g1;
    vtmp[b3 + 2 * 128 + f] = n2 + g2;
}

__global__ void zero_k(float* p, int n) {
    int i = blockIdx.x * blockDim.x + threadIdx.x;
    if (i < n) p[i] = 0.0f;
}

__global__ void counts_k(const int* batch, float* cnt, int N) {
    int i = blockIdx.x * blockDim.x + threadIdx.x;
    if (i < N) atomicAdd(&cnt[batch[i]], 1.0f);
}

// Sorted-segment sum: block handles [r0,r1) rows, thread = one column.
__global__ void seg_reduce_k(const float* src, const int* batch, float* dst,
                             int N, int Cc, int rows_per_blk)
{
    int c = threadIdx.x;
    int r0 = blockIdx.x * rows_per_blk;
    if (r0 >= N) return;
    int r1 = min(r0 + rows_per_blk, N);
    int cur = batch[r0];
    float s = 0.0f;
    for (int r = r0; r < r1; r++) {
        int b = batch[r];
        if (b != cur) {
            atomicAdd(&dst[(size_t)cur * Cc + c], s);
            s = 0.0f;
            cur = b;
        }
        s += src[(size_t)r * Cc + c];
    }
    atomicAdd(&dst[(size_t)cur * Cc + c], s);
}

__global__ void g1_k(const float* sum_x, const float* sum_vec, const float* cnt,
                     const float* scalar_l, const float* vector_l,
                     float* gcat, float* Av, int B)
{
    int idx = blockIdx.x * blockDim.x + threadIdx.x;
    if (idx >= B * 128) return;
    int b = idx >> 7, f = idx & 127;
    float invc = 1.0f / fmaxf(cnt[b], 1.0f);
    gcat[(size_t)b * 256 + f] = sum_x[(size_t)b * 128 + f] * invc;
    gcat[(size_t)b * 256 + 128 + f] = scalar_l[(size_t)b * 128 + f];
    #pragma unroll
    for (int d = 0; d < 3; d++) {
        size_t o = (size_t)b * 384 + d * 128 + f;
        Av[o] = sum_vec[o] * invc + vector_l[o];
    }
}

__global__ void g2_k(const float* scalar_l, const float* stmp,
                     const float* vector_l, const float* vtmpB,
                     float* sl, float* vl, int B)
{
    int idx = blockIdx.x * blockDim.x + threadIdx.x;
    if (idx >= B * 128) return;
    int b = idx >> 7, f = idx & 127;
    sl[(size_t)b * 128 + f] = scalar_l[(size_t)b * 128 + f] + stmp[(size_t)b * 128 + f];
    #pragma unroll
    for (int d = 0; d < 3; d++) {
        size_t o = (size_t)b * 384 + d * 128 + f;
        vl[o] = vector_l[o] + vtmpB[o];
    }
}

__global__ void g3_k(const float* hh, const float* sl, float* cat2, int B)
{
    int idx = blockIdx.x * blockDim.x + threadIdx.x;
    if (idx >= B * 128) return;
    int b = idx >> 7, f = idx & 127;
    float s = 1e-8f;
    #pragma unroll
    for (int d = 0; d < 3; d++) {
        float h2 = hh[((size_t)b * 3 + d) * 256 + 128 + f];
        s += h2 * h2;
    }
    cat2[(size_t)b * 256 + f] = sl[(size_t)b * 128 + f];
    cat2[(size_t)b * 256 + 128 + f] = sqrtf(s);
}

__global__ void g4_k(const float* sh, const float* sl, const float* hh,
                     const float* vl, float* out_sl, float* out_vl, int B)
{
    int idx = blockIdx.x * blockDim.x + threadIdx.x;
    if (idx >= B * 128) return;
    int b = idx >> 7, f = idx & 127;
    float s1 = sh[(size_t)b * 384 + f];
    float s2 = sh[(size_t)b * 384 + 128 + f];
    float s3 = sh[(size_t)b * 384 + 256 + f];
    out_sl[(size_t)b * 128 + f] = s2 + sl[(size_t)b * 128 + f] * tanhf(s3);
    #pragma unroll
    for (int d = 0; d < 3; d++) {
        float h1 = hh[((size_t)b * 3 + d) * 256 + f];
        size_t o = (size_t)b * 384 + d * 128 + f;
        out_vl[o] = s1 * h1 + vl[o];
    }
}

__global__ void ldelta_k(const float* vl_out, const float* W_ml, float* out, int rows)
{
    int warp = (blockIdx.x * blockDim.x + threadIdx.x) >> 5;
    int lane = threadIdx.x & 31;
    if (warp >= rows) return;
    const float* r = vl_out + (size_t)warp * 128;
    float s = 0.0f;
    #pragma unroll
    for (int i = 0; i < 4; i++) s += r[lane + i * 32] * W_ml[lane + i * 32];
    #pragma unroll
    for (int o = 16; o; o >>= 1) s += __shfl_down_sync(0xffffffff, s, o);
    if (lane == 0) out[warp] = s;
}

// ---------------------------------------------------------------------------
extern "C" void kernel_launch(void* const* d_in, const int* in_sizes, int n_in,
                              void* d_out, int out_size)
{
    const float* x        = (const float*)d_in[0];
    const float* scalar_l = (const float*)d_in[1];
    const float* vec      = (const float*)d_in[2];
    const float* vector_l = (const float*)d_in[3];
    const float* edge_f   = (const float*)d_in[4];
    const float* edge_ud  = (const float*)d_in[5];
    const int*   batch    = (const int*)d_in[6];
    const float* W_sg1 = (const float*)d_in[7];  const float* b_sg1 = (const float*)d_in[8];
    const float* W_sg2 = (const float*)d_in[9];  const float* b_sg2 = (const float*)d_in[10];
    const float* W_sl1 = (const float*)d_in[11]; const float* b_sl1 = (const float*)d_in[12];
    const float* W_sl2 = (const float*)d_in[13]; const float* b_sl2 = (const float*)d_in[14];
    const float* W_vg  = (const float*)d_in[15];
    const float* W_vl  = (const float*)d_in[16];
    const float* W_xp1 = (const float*)d_in[17]; const float* b_xp1 = (const float*)d_in[18];
    const float* W_xp2 = (const float*)d_in[19]; const float* b_xp2 = (const float*)d_in[20];
    const float* W_ep  = (const float*)d_in[21]; const float* b_ep  = (const float*)d_in[22];
    const float* W_vp  = (const float*)d_in[23];
    const float* W_lp1 = (const float*)d_in[24]; const float* b_lp1 = (const float*)d_in[25];
    const float* W_lp2 = (const float*)d_in[26]; const float* b_lp2 = (const float*)d_in[27];
    const float* W_ml  = (const float*)d_in[28];

    const int N = in_sizes[0] / FDIM;
    const int B = in_sizes[1] / FDIM;
    const int K_edge = in_sizes[4] / N;   // R = 64

    float* base = nullptr;
    cudaGetSymbolAddress((void**)&base, g_buf);

    const size_t NF = (size_t)N * FDIM;
    float* t_buf  = base;                 // [N,F]   t, later u
    float* xp_buf = base + NF;            // [N,3F]  xp, later vtmp
    float* ep_buf = base + 4 * NF;        // [N,3F]  ep, later vecn
    float* xn_buf = base + 7 * NF;        // [N,F]
    float* sm     = base + 8 * NF;        // small buffers
    float* sB      = sm;                       // B*128
    float* sum_x   = sm + 65536;               // B*128
    float* sum_vec = sm + 131072;              // B*384
    float* cnt     = sm + 327680;              // B
    float* gcat    = sm + 328192;              // B*256
    float* Av      = sm + 459264;              // B*384
    float* tmp1    = sm + 655872;              // B*128
    float* stmp    = sm + 721408;              // B*128
    float* vtmpB   = sm + 786944;              // B*384
    float* sl      = sm + 983552;              // B*128
    float* vl      = sm + 1049088;             // B*384
    float* hh      = sm + 1245696;             // B*3*256
    float* cat2    = sm + 1638912;             // B*256
    float* t2      = sm + 1769984;             // B*128
    float* sh      = sm + 1835520;             // B*384

    float* out = (float*)d_out;
    const size_t o0 = 0;
    const size_t o1 = NF;                          // hvec
    const size_t o2 = o1 + 3 * NF;                 // sl_out
    const size_t o3 = o2 + (size_t)B * 128;        // vl_out
    const size_t o4 = o3 + (size_t)B * 384;        // l_delta

    const int gM_N   = (N + 127) / 128;
    const int gM_3N  = (3 * N + 127) / 128;
    const int gM_B   = (B + 127) / 128;
    const int gM_3B  = (3 * B + 127) / 128;

    // ---- node phase ----
    tgemm_k<2><<<dim3(gM_N, 1), 256>>>(x, W_xp1, b_xp1, t_buf, N, 128, 128, nullptr, nullptr);
    tgemm_k<1><<<dim3(gM_N, 3), 256>>>(t_buf, W_xp2, b_xp2, xp_buf, N, 128, 384, nullptr, nullptr);
    tgemm_k<1><<<dim3(gM_N, 3), 256>>>(edge_f, W_ep, b_ep, ep_buf, N, K_edge, 384, nullptr, nullptr);
    {
        int tot = N * FDIM;
        node_elem_k<<<(tot + 255) / 256, 256>>>(xp_buf, ep_buf, x, vec, edge_ud,
                                                vector_l, batch, xn_buf, ep_buf, xp_buf, N);
    }
    tgemm_k<1><<<dim3(gM_B, 1), 256>>>(scalar_l, W_sl1 + 128 * 128, b_sl1, sB, B, 128, 128, nullptr, nullptr);
    tgemm_k<3><<<dim3(gM_N, 1), 256>>>(xn_buf, W_sl1, nullptr, t_buf, N, 128, 128, sB, batch);
    tgemm_k<4><<<dim3(gM_N, 1), 256>>>(t_buf, W_sl2, b_sl2, out + o0, N, 128, 128, xn_buf, nullptr);
    tgemm_k<5><<<dim3(gM_3N, 1), 256>>>(xp_buf, W_vl, nullptr, out + o1, 3 * N, 128, 128, ep_buf, nullptr);

    // ---- segment reduction ----
    {
        int nz = B * 128 + B * 384 + B;
        zero_k<<<(nz + 255) / 256, 256>>>(sum_x, nz);
        counts_k<<<(N + 255) / 256, 256>>>(batch, cnt, N);
        int rpb1 = 256;
        seg_reduce_k<<<(N + rpb1 - 1) / rpb1, 128>>>(out + o0, batch, sum_x, N, 128, rpb1);
        int rpb2 = 128;
        seg_reduce_k<<<(N + rpb2 - 1) / rpb2, 384>>>(out + o1, batch, sum_vec, N, 384, rpb2);
    }

    // ---- global phase ----
    int tB = B * 128;
    g1_k<<<(tB + 255) / 256, 256>>>(sum_x, sum_vec, cnt, scalar_l, vector_l, gcat, Av, B);
    tgemm_k<2><<<dim3(gM_B, 1), 256>>>(gcat, W_sg1, b_sg1, tmp1, B, 256, 128, nullptr, nullptr);
    tgemm_k<2><<<dim3(gM_B, 1), 256>>>(tmp1, W_sg2, b_sg2, stmp, B, 128, 128, nullptr, nullptr);
    tgemm_k<0><<<dim3(gM_3B, 1), 256>>>(Av, W_vg, nullptr, vtmpB, 3 * B, 128, 128, nullptr, nullptr);
    g2_k<<<(tB + 255) / 256, 256>>>(scalar_l, stmp, vector_l, vtmpB, sl, vl, B);
    tgemm_k<0><<<dim3(gM_3B, 2), 256>>>(vl, W_vp, nullptr, hh, 3 * B, 128, 256, nullptr, nullptr);
    g3_k<<<(tB + 255) / 256, 256>>>(hh, sl, cat2, B);
    tgemm_k<2><<<dim3(gM_B, 1), 256>>>(cat2, W_lp1, b_lp1, t2, B, 256, 128, nullptr, nullptr);
    tgemm_k<1><<<dim3(gM_B, 3), 256>>>(t2, W_lp2, b_lp2, sh, B, 128, 384, nullptr, nullptr);
    g4_k<<<(tB + 255) / 256, 256>>>(sh, sl, hh, vl, out + o2, out + o3, B);
    {
        int rows = 3 * B;
        int thr = 256;
        int blks = (rows * 32 + thr - 1) / thr;
        ldelta_k<<<blks, thr>>>(out + o3, W_ml, out + o4, rows);
    }
}

// round 3
// speedup vs baseline: 1.7605x; 1.0212x over previous
#include <cuda_runtime.h>
#include <math.h>
#include <stdint.h>

#define FDIM 128
#define SSCALE 1.6666666666666667f   // 1/0.6
#define INV3 0.5773502691896258f     // 1/sqrt(3)
#define INVH 0.08838834764831845f    // 1/sqrt(128)

// Scratch: 8*N*F node buffers + ~2.1M floats for global phase (N<=120000)
static __device__ float g_buf[125000000];

__device__ __forceinline__ float ssilu_f(float v) {
    return v * SSCALE / (1.0f + __expf(-v));
}

__device__ __forceinline__ float to_tf32_f(float x) {
    uint32_t r;
    asm("cvt.rna.tf32.f32 %0, %1;" : "=r"(r) : "f"(x));
    return __uint_as_float(r);
}

__device__ __forceinline__ void mma_tf32(float* d,
                                         const uint32_t* a,
                                         const uint32_t* b,
                                         const float* c) {
    asm volatile(
        "mma.sync.aligned.m16n8k8.row.col.f32.tf32.tf32.f32 "
        "{%0,%1,%2,%3},{%4,%5,%6,%7},{%8,%9},{%10,%11,%12,%13};"
        : "=f"(d[0]), "=f"(d[1]), "=f"(d[2]), "=f"(d[3])
        : "r"(a[0]), "r"(a[1]), "r"(a[2]), "r"(a[3]),
          "r"(b[0]), "r"(b[1]),
          "f"(c[0]), "f"(c[1]), "f"(c[2]), "f"(c[3]));
}

// ---------------------------------------------------------------------------
// Tensor-core tf32 GEMM, double-buffered software pipeline.
// C[M,Cc] = A[M,K] @ W[K,Cc]  (+ fused epilogues)
// BM=128, BN=128, BK=16, 256 threads (8 warps, 2M x 4N), warp tile 64x32.
// EPI: 0=plain 1=+bias 2=ssilu(+bias) 3=ssilu(+extra[bidx[r]*128+c])
//      4=ssilu(+bias)+extra[r*128+c]  5=+extra[r*128+c]
//      6=(v+bias)*extra[r*Cc+c]*INV3   (producer fusion for p = xp*ep/sqrt3)
// Requires K % 16 == 0, Cc % 128 == 0.
// ---------------------------------------------------------------------------
template <int EPI>
__global__ void __launch_bounds__(256, 2) tgemm_k(
    const float* __restrict__ A, const float* __restrict__ W,
    const float* __restrict__ bias, float* __restrict__ C,
    int M, int K, int Cc,
    const float* __restrict__ extra, const int* __restrict__ bidx)
{
    __shared__ float As[2][16][136];   // [buf][k][m], pad 8
    __shared__ float Ws[2][16][136];   // [buf][k][n]

    const int tid = threadIdx.x;
    const int row0 = blockIdx.x * 128;
    const int col0 = blockIdx.y * 128;
    const int warp = tid >> 5;
    const int lane = tid & 31;
    const int wm = warp & 1;        // 0..1  -> 64-row slab
    const int wn = warp >> 1;       // 0..3  -> 32-col slab
    const int g = lane >> 2;        // groupID 0..7
    const int tig = lane & 3;       // thread-in-group 0..3

    // loader task geometry (2 tasks per thread each for A and W)
    const int a_row0 = tid >> 2;            // task t: row = a_row0 + t*64? no: id=tid+t*256
    const int a_kc   = (tid & 3) * 4;
    const int w_kr   = tid >> 5;
    const int w_c4   = (tid & 31) * 4;

    float acc[4][4][4];
    #pragma unroll
    for (int i = 0; i < 4; i++)
        #pragma unroll
        for (int j = 0; j < 4; j++)
            #pragma unroll
            for (int q = 0; q < 4; q++) acc[i][j][q] = 0.0f;

    const int iters = K >> 4;
    float4 a_st[2], w_st[2];

    // ---- prologue: load tile 0 ----
    #pragma unroll
    for (int t = 0; t < 2; t++) {
        int row = a_row0 + t * 64;
        int grow = row0 + row;
        a_st[t] = (grow < M)
            ? *reinterpret_cast<const float4*>(A + (size_t)grow * K + a_kc)
            : make_float4(0.f, 0.f, 0.f, 0.f);
        int kr = w_kr + t * 8;
        w_st[t] = *reinterpret_cast<const float4*>(W + (size_t)kr * Cc + col0 + w_c4);
    }
    #pragma unroll
    for (int t = 0; t < 2; t++) {
        int row = a_row0 + t * 64;
        As[0][a_kc + 0][row] = to_tf32_f(a_st[t].x);
        As[0][a_kc + 1][row] = to_tf32_f(a_st[t].y);
        As[0][a_kc + 2][row] = to_tf32_f(a_st[t].z);
        As[0][a_kc + 3][row] = to_tf32_f(a_st[t].w);
        int kr = w_kr + t * 8;
        float4 wc = make_float4(to_tf32_f(w_st[t].x), to_tf32_f(w_st[t].y),
                                to_tf32_f(w_st[t].z), to_tf32_f(w_st[t].w));
        *reinterpret_cast<float4*>(&Ws[0][kr][w_c4]) = wc;
    }
    __syncthreads();

    for (int it = 0; it < iters; it++) {
        const int cur = it & 1;
        const bool has_next = (it + 1 < iters);

        // issue next tile's global loads early
        if (has_next) {
            int k0 = (it + 1) << 4;
            #pragma unroll
            for (int t = 0; t < 2; t++) {
                int row = a_row0 + t * 64;
                int grow = row0 + row;
                a_st[t] = (grow < M)
                    ? *reinterpret_cast<const float4*>(A + (size_t)grow * K + k0 + a_kc)
                    : make_float4(0.f, 0.f, 0.f, 0.f);
                int kr = w_kr + t * 8;
                w_st[t] = *reinterpret_cast<const float4*>(
                    W + (size_t)(k0 + kr) * Cc + col0 + w_c4);
            }
        }

        // compute on current buffer
        #pragma unroll
        for (int s = 0; s < 2; s++) {
            const int kb = s * 8;
            uint32_t afr[4][4];
            uint32_t bfr[4][2];
            #pragma unroll
            for (int mi = 0; mi < 4; mi++) {
                int mr = wm * 64 + mi * 16 + g;
                afr[mi][0] = __float_as_uint(As[cur][kb + tig][mr]);
                afr[mi][1] = __float_as_uint(As[cur][kb + tig][mr + 8]);
                afr[mi][2] = __float_as_uint(As[cur][kb + tig + 4][mr]);
                afr[mi][3] = __float_as_uint(As[cur][kb + tig + 4][mr + 8]);
            }
            #pragma unroll
            for (int nj = 0; nj < 4; nj++) {
                int nc = wn * 32 + nj * 8 + g;
                bfr[nj][0] = __float_as_uint(Ws[cur][kb + tig][nc]);
                bfr[nj][1] = __float_as_uint(Ws[cur][kb + tig + 4][nc]);
            }
            #pragma unroll
            for (int mi = 0; mi < 4; mi++)
                #pragma unroll
                for (int nj = 0; nj < 4; nj++)
                    mma_tf32(acc[mi][nj], afr[mi], bfr[nj], acc[mi][nj]);
        }

        // stage next tile into the other buffer
        if (has_next) {
            const int nxt = (it + 1) & 1;
            #pragma unroll
            for (int t = 0; t < 2; t++) {
                int row = a_row0 + t * 64;
                As[nxt][a_kc + 0][row] = to_tf32_f(a_st[t].x);
                As[nxt][a_kc + 1][row] = to_tf32_f(a_st[t].y);
                As[nxt][a_kc + 2][row] = to_tf32_f(a_st[t].z);
                As[nxt][a_kc + 3][row] = to_tf32_f(a_st[t].w);
                int kr = w_kr + t * 8;
                float4 wc = make_float4(to_tf32_f(w_st[t].x), to_tf32_f(w_st[t].y),
                                        to_tf32_f(w_st[t].z), to_tf32_f(w_st[t].w));
                *reinterpret_cast<float4*>(&Ws[nxt][kr][w_c4]) = wc;
            }
        }
        __syncthreads();
    }

    // Epilogue
    #pragma unroll
    for (int mi = 0; mi < 4; mi++) {
        int rbase = row0 + wm * 64 + mi * 16 + g;
        #pragma unroll
        for (int half = 0; half < 2; half++) {
            int r = rbase + half * 8;
            if (r >= M) continue;
            int rb = 0;
            if (EPI == 3) rb = bidx[r];
            #pragma unroll
            for (int nj = 0; nj < 4; nj++) {
                int c = col0 + wn * 32 + nj * 8 + tig * 2;
                #pragma unroll
                for (int e = 0; e < 2; e++) {
                    float v = acc[mi][nj][half * 2 + e];
                    int cc = c + e;
                    if (EPI == 1) v += bias[cc];
                    else if (EPI == 2) v = ssilu_f(v + bias[cc]);
                    else if (EPI == 3) v = ssilu_f(v + extra[(size_t)rb * 128 + cc]);
                    else if (EPI == 4) v = ssilu_f(v + bias[cc]) + extra[(size_t)r * 128 + cc];
                    else if (EPI == 5) v = v + extra[(size_t)r * 128 + cc];
                    else if (EPI == 6) v = (v + bias[cc]) * extra[(size_t)r * Cc + cc] * INV3;
                    C[(size_t)r * Cc + cc] = v;
                }
            }
        }
    }
}

// ---------------------------------------------------------------------------
// Node-level elementwise fusion. p = xp*ep*inv3 already computed by EPI-6 GEMM.
// vecn -> ep_buf (free), vtmp -> p buffer (aliased; reads precede writes).
// ---------------------------------------------------------------------------
__global__ void node_elem_k(
    const float* p, const float* x,
    const float* vec, const float* ud, const float* vl_g,
    const int* batch, float* xn, float* vecn, float* vtmp, int N)
{
    int idx = blockIdx.x * blockDim.x + threadIdx.x;
    if (idx >= N * FDIM) return;
    int n = idx >> 7;
    int f = idx & 127;
    size_t b3 = (size_t)n * 384;

    float p1 = p[b3 + f], p2 = p[b3 + 128 + f], p3 = p[b3 + 256 + f];

    xn[(size_t)n * 128 + f] = p3 + x[(size_t)n * 128 + f];

    int b = batch[n];
    float u0 = ud[n * 3 + 0], u1 = ud[n * 3 + 1], u2 = ud[n * 3 + 2];
    float v0 = vec[b3 + 0 * 128 + f];
    float v1 = vec[b3 + 1 * 128 + f];
    float v2 = vec[b3 + 2 * 128 + f];
    float g0 = vl_g[(size_t)b * 384 + 0 * 128 + f];
    float g1 = vl_g[(size_t)b * 384 + 1 * 128 + f];
    float g2 = vl_g[(size_t)b * 384 + 2 * 128 + f];

    float n0 = (p1 * v0 + p2 * u0) * INVH;
    float n1 = (p1 * v1 + p2 * u1) * INVH;
    float n2 = (p1 * v2 + p2 * u2) * INVH;
    vecn[b3 + 0 * 128 + f] = n0;
    vecn[b3 + 1 * 128 + f] = n1;
    vecn[b3 + 2 * 128 + f] = n2;
    vtmp[b3 + 0 * 128 + f] = n0 + g0;
    vtmp[b3 + 1 * 128 + f] = n1 + g1;
    vtmp[b3 + 2 * 128 + f] = n2 + g2;
}

__global__ void zero_k(float* p, int n) {
    int i = blockIdx.x * blockDim.x + threadIdx.x;
    if (i < n) p[i] = 0.0f;
}

__global__ void counts_k(const int* batch, float* cnt, int N) {
    int i = blockIdx.x * blockDim.x + threadIdx.x;
    if (i < N) atomicAdd(&cnt[batch[i]], 1.0f);
}

// Sorted-segment sum: block handles [r0,r1) rows, thread = one column.
__global__ void seg_reduce_k(const float* src, const int* batch, float* dst,
                             int N, int Cc, int rows_per_blk)
{
    int c = threadIdx.x;
    int r0 = blockIdx.x * rows_per_blk;
    if (r0 >= N) return;
    int r1 = min(r0 + rows_per_blk, N);
    int cur = batch[r0];
    float s = 0.0f;
    for (int r = r0; r < r1; r++) {
        int b = batch[r];
        if (b != cur) {
            atomicAdd(&dst[(size_t)cur * Cc + c], s);
            s = 0.0f;
            cur = b;
        }
        s += src[(size_t)r * Cc + c];
    }
    atomicAdd(&dst[(size_t)cur * Cc + c], s);
}

__global__ void g1_k(const float* sum_x, const float* sum_vec, const float* cnt,
                     const float* scalar_l, const float* vector_l,
                     float* gcat, float* Av, int B)
{
    int idx = blockIdx.x * blockDim.x + threadIdx.x;
    if (idx >= B * 128) return;
    int b = idx >> 7, f = idx & 127;
    float invc = 1.0f / fmaxf(cnt[b], 1.0f);
    gcat[(size_t)b * 256 + f] = sum_x[(size_t)b * 128 + f] * invc;
    gcat[(size_t)b * 256 + 128 + f] = scalar_l[(size_t)b * 128 + f];
    #pragma unroll
    for (int d = 0; d < 3; d++) {
        size_t o = (size_t)b * 384 + d * 128 + f;
        Av[o] = sum_vec[o] * invc + vector_l[o];
    }
}

__global__ void g2_k(const float* scalar_l, const float* stmp,
                     const float* vector_l, const float* vtmpB,
                     float* sl, float* vl, int B)
{
    int idx = blockIdx.x * blockDim.x + threadIdx.x;
    if (idx >= B * 128) return;
    int b = idx >> 7, f = idx & 127;
    sl[(size_t)b * 128 + f] = scalar_l[(size_t)b * 128 + f] + stmp[(size_t)b * 128 + f];
    #pragma unroll
    for (int d = 0; d < 3; d++) {
        size_t o = (size_t)b * 384 + d * 128 + f;
        vl[o] = vector_l[o] + vtmpB[o];
    }
}

__global__ void g3_k(const float* hh, const float* sl, float* cat2, int B)
{
    int idx = blockIdx.x * blockDim.x + threadIdx.x;
    if (idx >= B * 128) return;
    int b = idx >> 7, f = idx & 127;
    float s = 1e-8f;
    #pragma unroll
    for (int d = 0; d < 3; d++) {
        float h2 = hh[((size_t)b * 3 + d) * 256 + 128 + f];
        s += h2 * h2;
    }
    cat2[(size_t)b * 256 + f] = sl[(size_t)b * 128 + f];
    cat2[(size_t)b * 256 + 128 + f] = sqrtf(s);
}

__global__ void g4_k(const float* sh, const float* sl, const float* hh,
                     const float* vl, float* out_sl, float* out_vl, int B)
{
    int idx = blockIdx.x * blockDim.x + threadIdx.x;
    if (idx >= B * 128) return;
    int b = idx >> 7, f = idx & 127;
    float s1 = sh[(size_t)b * 384 + f];
    float s2 = sh[(size_t)b * 384 + 128 + f];
    float s3 = sh[(size_t)b * 384 + 256 + f];
    out_sl[(size_t)b * 128 + f] = s2 + sl[(size_t)b * 128 + f] * tanhf(s3);
    #pragma unroll
    for (int d = 0; d < 3; d++) {
        float h1 = hh[((size_t)b * 3 + d) * 256 + f];
        size_t o = (size_t)b * 384 + d * 128 + f;
        out_vl[o] = s1 * h1 + vl[o];
    }
}

__global__ void ldelta_k(const float* vl_out, const float* W_ml, float* out, int rows)
{
    int warp = (blockIdx.x * blockDim.x + threadIdx.x) >> 5;
    int lane = threadIdx.x & 31;
    if (warp >= rows) return;
    const float* r = vl_out + (size_t)warp * 128;
    float s = 0.0f;
    #pragma unroll
    for (int i = 0; i < 4; i++) s += r[lane + i * 32] * W_ml[lane + i * 32];
    #pragma unroll
    for (int o = 16; o; o >>= 1) s += __shfl_down_sync(0xffffffff, s, o);
    if (lane == 0) out[warp] = s;
}

// ---------------------------------------------------------------------------
extern "C" void kernel_launch(void* const* d_in, const int* in_sizes, int n_in,
                              void* d_out, int out_size)
{
    const float* x        = (const float*)d_in[0];
    const float* scalar_l = (const float*)d_in[1];
    const float* vec      = (const float*)d_in[2];
    const float* vector_l = (const float*)d_in[3];
    const float* edge_f   = (const float*)d_in[4];
    const float* edge_ud  = (const float*)d_in[5];
    const int*   batch    = (const int*)d_in[6];
    const float* W_sg1 = (const float*)d_in[7];  const float* b_sg1 = (const float*)d_in[8];
    const float* W_sg2 = (const float*)d_in[9];  const float* b_sg2 = (const float*)d_in[10];
    const float* W_sl1 = (const float*)d_in[11]; const float* b_sl1 = (const float*)d_in[12];
    const float* W_sl2 = (const float*)d_in[13]; const float* b_sl2 = (const float*)d_in[14];
    const float* W_vg  = (const float*)d_in[15];
    const float* W_vl  = (const float*)d_in[16];
    const float* W_xp1 = (const float*)d_in[17]; const float* b_xp1 = (const float*)d_in[18];
    const float* W_xp2 = (const float*)d_in[19]; const float* b_xp2 = (const float*)d_in[20];
    const float* W_ep  = (const float*)d_in[21]; const float* b_ep  = (const float*)d_in[22];
    const float* W_vp  = (const float*)d_in[23];
    const float* W_lp1 = (const float*)d_in[24]; const float* b_lp1 = (const float*)d_in[25];
    const float* W_lp2 = (const float*)d_in[26]; const float* b_lp2 = (const float*)d_in[27];
    const float* W_ml  = (const float*)d_in[28];

    const int N = in_sizes[0] / FDIM;
    const int B = in_sizes[1] / FDIM;
    const int K_edge = in_sizes[4] / N;   // R = 64

    float* base = nullptr;
    cudaGetSymbolAddress((void**)&base, g_buf);

    const size_t NF = (size_t)N * FDIM;
    float* t_buf  = base;                 // [N,F]   t, later u
    float* xp_buf = base + NF;            // [N,3F]  xp -> p -> vtmp
    float* ep_buf = base + 4 * NF;        // [N,3F]  vecn
    float* xn_buf = base + 7 * NF;        // [N,F]
    float* sm     = base + 8 * NF;        // small buffers
    float* sB      = sm;                       // B*128
    float* sum_x   = sm + 65536;               // B*128
    float* sum_vec = sm + 131072;              // B*384
    float* cnt     = sm + 327680;              // B
    float* gcat    = sm + 328192;              // B*256
    float* Av      = sm + 459264;              // B*384
    float* tmp1    = sm + 655872;              // B*128
    float* stmp    = sm + 721408;              // B*128
    float* vtmpB   = sm + 786944;              // B*384
    float* sl      = sm + 983552;              // B*128
    float* vl      = sm + 1049088;             // B*384
    float* hh      = sm + 1245696;             // B*3*256
    float* cat2    = sm + 1638912;             // B*256
    float* t2      = sm + 1769984;             // B*128
    float* sh      = sm + 1835520;             // B*384

    float* out = (float*)d_out;
    const size_t o0 = 0;
    const size_t o1 = NF;                          // hvec
    const size_t o2 = o1 + 3 * NF;                 // sl_out
    const size_t o3 = o2 + (size_t)B * 128;        // vl_out
    const size_t o4 = o3 + (size_t)B * 384;        // l_delta

    const int gM_N   = (N + 127) / 128;
    const int gM_3N  = (3 * N + 127) / 128;
    const int gM_B   = (B + 127) / 128;
    const int gM_3B  = (3 * B + 127) / 128;

    // ---- node phase ----
    // t = ssilu(x @ W_xp1 + b_xp1)
    tgemm_k<2><<<dim3(gM_N, 1), 256>>>(x, W_xp1, b_xp1, t_buf, N, 128, 128, nullptr, nullptr);
    // xp = t @ W_xp2 + b_xp2
    tgemm_k<1><<<dim3(gM_N, 3), 256>>>(t_buf, W_xp2, b_xp2, xp_buf, N, 128, 384, nullptr, nullptr);
    // p = (edge_feat @ W_ep + b_ep) * xp * INV3   (in place over xp_buf)
    tgemm_k<6><<<dim3(gM_N, 3), 256>>>(edge_f, W_ep, b_ep, xp_buf, N, K_edge, 384, xp_buf, nullptr);
    {
        int tot = N * FDIM;
        node_elem_k<<<(tot + 255) / 256, 256>>>(xp_buf, x, vec, edge_ud,
                                                vector_l, batch, xn_buf, ep_buf, xp_buf, N);
    }
    tgemm_k<1><<<dim3(gM_B, 1), 256>>>(scalar_l, W_sl1 + 128 * 128, b_sl1, sB, B, 128, 128, nullptr, nullptr);
    tgemm_k<3><<<dim3(gM_N, 1), 256>>>(xn_buf, W_sl1, nullptr, t_buf, N, 128, 128, sB, batch);
    tgemm_k<4><<<dim3(gM_N, 1), 256>>>(t_buf, W_sl2, b_sl2, out + o0, N, 128, 128, xn_buf, nullptr);
    tgemm_k<5><<<dim3(gM_3N, 1), 256>>>(xp_buf, W_vl, nullptr, out + o1, 3 * N, 128, 128, ep_buf, nullptr);

    // ---- segment reduction ----
    {
        int nz = B * 128 + B * 384 + B;
        zero_k<<<(nz + 255) / 256, 256>>>(sum_x, nz);
        counts_k<<<(N + 255) / 256, 256>>>(batch, cnt, N);
        int rpb1 = 256;
        seg_reduce_k<<<(N + rpb1 - 1) / rpb1, 128>>>(out + o0, batch, sum_x, N, 128, rpb1);
        int rpb2 = 128;
        seg_reduce_k<<<(N + rpb2 - 1) / rpb2, 384>>>(out + o1, batch, sum_vec, N, 384, rpb2);
    }

    // ---- global phase ----
    int tB = B * 128;
    g1_k<<<(tB + 255) / 256, 256>>>(sum_x, sum_vec, cnt, scalar_l, vector_l, gcat, Av, B);
    tgemm_k<2><<<dim3(gM_B, 1), 256>>>(gcat, W_sg1, b_sg1, tmp1, B, 256, 128, nullptr, nullptr);
    tgemm_k<2><<<dim3(gM_B, 1), 256>>>(tmp1, W_sg2, b_sg2, stmp, B, 128, 128, nullptr, nullptr);
    tgemm_k<0><<<dim3(gM_3B, 1), 256>>>(Av, W_vg, nullptr, vtmpB, 3 * B, 128, 128, nullptr, nullptr);
    g2_k<<<(tB + 255) / 256, 256>>>(scalar_l, stmp, vector_l, vtmpB, sl, vl, B);
    tgemm_k<0><<<dim3(gM_3B, 2), 256>>>(vl, W_vp, nullptr, hh, 3 * B, 128, 256, nullptr, nullptr);
    g3_k<<<(tB + 255) / 256, 256>>>(hh, sl, cat2, B);
    tgemm_k<2><<<dim3(gM_B, 1), 256>>>(cat2, W_lp1, b_lp1, t2, B, 256, 128, nullptr, nullptr);
    tgemm_k<1><<<dim3(gM_B, 3), 256>>>(t2, W_lp2, b_lp2, sh, B, 128, 384, nullptr, nullptr);
    g4_k<<<(tB + 255) / 256, 256>>>(sh, sl, hh, vl, out + o2, out + o3, B);
    {
        int rows = 3 * B;
        int thr = 256;
        int blks = (rows * 32 + thr - 1) / thr;
        ldelta_k<<<blks, thr>>>(out + o3, W_ml, out + o4, rows);
    }
}